// round 8
// baseline (speedup 1.0000x reference)
#include <cuda_runtime.h>

// Problem constants (fixed by the reference setup_inputs)
#define BB 8
#define CC 512
#define RR 128
#define HW (128 * 128)
#define NPLANE (BB * CC)

// Scratch (no allocations allowed in kernel_launch)
__device__ float g_sums[NPLANE];          // per-plane sums
__device__ float g_y1[BB * RR];           // relu6(w_guide @ mean) per batch

// ---------------------------------------------------------------------------
// Plane reduce body: one 256-thread CTA sums one 16384-float plane.
// ---------------------------------------------------------------------------
__device__ __forceinline__ void plane_reduce(const float* __restrict__ x,
                                             int plane, int tid) {
    const float4* __restrict__ p =
        reinterpret_cast<const float4*>(x + (size_t)plane * HW);
    float s = 0.0f;
#pragma unroll
    for (int i = 0; i < HW / 4 / 256; ++i) {
        float4 v = p[tid + i * 256];
        s += (v.x + v.y) + (v.z + v.w);
    }
#pragma unroll
    for (int o = 16; o > 0; o >>= 1)
        s += __shfl_xor_sync(0xffffffffu, s, o);

    __shared__ float ws[8];
    if ((tid & 31) == 0) ws[tid >> 5] = s;
    __syncthreads();
    if (tid < 8) {
        float t = ws[tid];
#pragma unroll
        for (int o = 4; o > 0; o >>= 1)
            t += __shfl_xor_sync(0x000000ffu, t, o);
        if (tid == 0) g_sums[plane] = t;
    }
}

// ---------------------------------------------------------------------------
// Plane add body with inline bias: warp 0 computes
//   bias = relu6(BN(dot(w_fuse[c,:], y1[b])))
// then all warps stream out = x + bias (reads evict-first: data dead after;
// stores evict-first: keep L2 for the concurrent reduce stream).
// ---------------------------------------------------------------------------
__device__ __forceinline__ void plane_add(
    const float* __restrict__ x, float* __restrict__ out,
    const float* __restrict__ w_fuse,
    const float* __restrict__ bn_gamma, const float* __restrict__ bn_beta,
    const float* __restrict__ bn_mean,  const float* __restrict__ bn_var,
    int b, int c, int tid) {
    __shared__ float bsh;
    const int wid  = tid >> 5;
    const int lane = tid & 31;

    if (wid == 0) {
        const float4* __restrict__ row =
            reinterpret_cast<const float4*>(w_fuse + (size_t)c * RR);
        const float4* __restrict__ y14 =
            reinterpret_cast<const float4*>(g_y1 + b * RR);
        float4 w = row[lane];
        float4 y = y14[lane];
        float acc = w.x * y.x;
        acc = fmaf(w.y, y.y, acc);
        acc = fmaf(w.z, y.z, acc);
        acc = fmaf(w.w, y.w, acc);
#pragma unroll
        for (int o = 16; o > 0; o >>= 1)
            acc += __shfl_xor_sync(0xffffffffu, acc, o);
        if (lane == 0) {
            const float inv_std = rsqrtf(bn_var[c] + 1e-5f);
            float v = fmaf((acc - bn_mean[c]) * inv_std, bn_gamma[c], bn_beta[c]);
            bsh = fminf(fmaxf(v, 0.0f), 6.0f);
        }
    }
    __syncthreads();
    const float bias = bsh;

    const int plane = b * CC + c;
    const float4* __restrict__ p =
        reinterpret_cast<const float4*>(x + (size_t)plane * HW);
    float4* __restrict__ o =
        reinterpret_cast<float4*>(out + (size_t)plane * HW);
#pragma unroll
    for (int i = 0; i < HW / 4 / 256; ++i) {
        float4 v = __ldcs(&p[tid + i * 256]);
        v.x += bias; v.y += bias; v.z += bias; v.w += bias;
        __stcs(&o[tid + i * 256], v);
    }
}

// ---------------------------------------------------------------------------
// Mid body: y1[b][r] = relu6((w_guide[r,:] @ sums[b]) / HW).
// One warp per output row r: 4 coalesced float4 loads per lane + shuffle.
// ---------------------------------------------------------------------------
__device__ __forceinline__ void mid_body(const float* __restrict__ w_guide,
                                         int b, int r, int lane) {
    const float4* __restrict__ row =
        reinterpret_cast<const float4*>(w_guide + (size_t)r * CC);
    const float4* __restrict__ s4 =
        reinterpret_cast<const float4*>(g_sums + (size_t)b * CC);

    float acc = 0.0f;
#pragma unroll
    for (int j = 0; j < 4; ++j) {
        float4 w = row[lane + 32 * j];
        float4 y = s4[lane + 32 * j];
        acc = fmaf(w.x, y.x, acc);
        acc = fmaf(w.y, y.y, acc);
        acc = fmaf(w.z, y.z, acc);
        acc = fmaf(w.w, y.w, acc);
    }
#pragma unroll
    for (int o = 16; o > 0; o >>= 1)
        acc += __shfl_xor_sync(0xffffffffu, acc, o);
    if (lane == 0) {
        float v = acc * (1.0f / (float)HW);
        g_y1[b * RR + r] = fminf(fmaxf(v, 0.0f), 6.0f);
    }
}

// ---------------------------------------------------------------------------
// Unified phase kernel. CTA ranges (by blockIdx.x):
//   [0, nAdd)            : add  batch addB   (nAdd = 512 or 0)
//   [nAdd, nAdd+nMid)    : mid  batch midB   (nMid = 16 or 0; 8 warps/CTA)
//   [nAdd+nMid, ...)     : red  batch redB   (512 or 0)
// All dependencies cross launch boundaries — no sync instructions anywhere.
// ---------------------------------------------------------------------------
__global__ __launch_bounds__(256) void phase_kernel(
    const float* __restrict__ x, float* __restrict__ out,
    const float* __restrict__ w_guide,
    const float* __restrict__ w_fuse,
    const float* __restrict__ bn_gamma, const float* __restrict__ bn_beta,
    const float* __restrict__ bn_mean,  const float* __restrict__ bn_var,
    int addB, int midB, int redB, int nAdd, int nMid) {
    const int bid = blockIdx.x;
    const int tid = threadIdx.x;

    if (bid < nAdd) {
        plane_add(x, out, w_fuse, bn_gamma, bn_beta, bn_mean, bn_var,
                  addB, bid, tid);
    } else if (bid < nAdd + nMid) {
        const int r = (bid - nAdd) * 8 + (tid >> 5);
        mid_body(w_guide, midB, r, tid & 31);
    } else {
        plane_reduce(x, redB * CC + (bid - nAdd - nMid), tid);
    }
}

extern "C" void kernel_launch(void* const* d_in, const int* in_sizes, int n_in,
                              void* d_out, int out_size) {
    const float* x        = (const float*)d_in[0];
    const float* w_guide  = (const float*)d_in[1];
    const float* w_fuse   = (const float*)d_in[2];
    const float* bn_gamma = (const float*)d_in[3];
    const float* bn_beta  = (const float*)d_in[4];
    const float* bn_mean  = (const float*)d_in[5];
    const float* bn_var   = (const float*)d_in[6];
    float* out = (float*)d_out;

    const int NMID = RR / 8;   // 16 CTAs, 8 warps each

    // Depth-2 pipeline: launch p does add(p-2) + mid(p-1) + red(p).
    for (int p = 0; p <= BB + 1; ++p) {
        const int addB = p - 2;
        const int midB = p - 1;
        const int redB = p;
        const int nAdd = (addB >= 0 && addB < BB) ? CC : 0;
        const int nMid = (midB >= 0 && midB < BB) ? NMID : 0;
        const int nRed = (redB < BB) ? CC : 0;
        phase_kernel<<<nAdd + nMid + nRed, 256>>>(
            x, out, w_guide, w_fuse, bn_gamma, bn_beta, bn_mean, bn_var,
            addB, midB, redB, nAdd, nMid);
    }
}

// round 9
// speedup vs baseline: 1.1930x; 1.1930x over previous
#include <cuda_runtime.h>

// Problem constants (fixed by the reference setup_inputs)
#define BB 8
#define CC 512
#define RR 128
#define HW (128 * 128)
#define NPLANE (BB * CC)
#define HV (HW / 4 / 2)           // float4 elements per HALF plane (2048)

// Scratch (no allocations allowed in kernel_launch)
__device__ float g_part[NPLANE * 2];      // half-plane partial sums
__device__ float g_y1[BB * RR];           // relu6(w_guide @ mean) per batch

// ---------------------------------------------------------------------------
// Half-plane reduce: one 256-thread CTA sums 8192 floats (8 float4/thread).
// ---------------------------------------------------------------------------
__device__ __forceinline__ void half_reduce(const float* __restrict__ x,
                                            int plane, int half, int tid) {
    const float4* __restrict__ p =
        reinterpret_cast<const float4*>(x + (size_t)plane * HW) + half * HV;
    float s = 0.0f;
#pragma unroll
    for (int i = 0; i < HV / 256; ++i) {
        float4 v = p[tid + i * 256];
        s += (v.x + v.y) + (v.z + v.w);
    }
#pragma unroll
    for (int o = 16; o > 0; o >>= 1)
        s += __shfl_xor_sync(0xffffffffu, s, o);

    __shared__ float ws[8];
    if ((tid & 31) == 0) ws[tid >> 5] = s;
    __syncthreads();
    if (tid < 8) {
        float t = ws[tid];
#pragma unroll
        for (int o = 4; o > 0; o >>= 1)
            t += __shfl_xor_sync(0x000000ffu, t, o);
        if (tid == 0) g_part[plane * 2 + half] = t;
    }
}

// ---------------------------------------------------------------------------
// Half-plane add with inline bias: warp 0 computes
//   bias = relu6(BN(dot(w_fuse[c,:], y1[b])))  (duplicated across both halves)
// then all warps stream out = x + bias. Evict-first reads (dead after) and
// stores (keep L2 for the concurrent reduce stream).
// ---------------------------------------------------------------------------
__device__ __forceinline__ void half_add(
    const float* __restrict__ x, float* __restrict__ out,
    const float* __restrict__ w_fuse,
    const float* __restrict__ bn_gamma, const float* __restrict__ bn_beta,
    const float* __restrict__ bn_mean,  const float* __restrict__ bn_var,
    int b, int c, int half, int tid) {
    __shared__ float bsh;
    const int lane = tid & 31;

    if (tid < 32) {
        const float4* __restrict__ row =
            reinterpret_cast<const float4*>(w_fuse + (size_t)c * RR);
        const float4* __restrict__ y14 =
            reinterpret_cast<const float4*>(g_y1 + b * RR);
        float4 w = row[lane];
        float4 y = y14[lane];
        float acc = w.x * y.x;
        acc = fmaf(w.y, y.y, acc);
        acc = fmaf(w.z, y.z, acc);
        acc = fmaf(w.w, y.w, acc);
#pragma unroll
        for (int o = 16; o > 0; o >>= 1)
            acc += __shfl_xor_sync(0xffffffffu, acc, o);
        if (lane == 0) {
            const float inv_std = rsqrtf(bn_var[c] + 1e-5f);
            float v = fmaf((acc - bn_mean[c]) * inv_std, bn_gamma[c], bn_beta[c]);
            bsh = fminf(fmaxf(v, 0.0f), 6.0f);
        }
    }
    __syncthreads();
    const float bias = bsh;

    const int plane = b * CC + c;
    const float4* __restrict__ p =
        reinterpret_cast<const float4*>(x + (size_t)plane * HW) + half * HV;
    float4* __restrict__ o =
        reinterpret_cast<float4*>(out + (size_t)plane * HW) + half * HV;
#pragma unroll
    for (int i = 0; i < HV / 256; ++i) {
        float4 v = __ldcs(&p[tid + i * 256]);
        v.x += bias; v.y += bias; v.z += bias; v.w += bias;
        __stcs(&o[tid + i * 256], v);
    }
}

// ---------------------------------------------------------------------------
// Mid body: y1[b][r] = relu6((w_guide[r,:] @ sums[b]) / HW), one warp per r.
// sums[b][c] = g_part[(b*CC+c)*2] + g_part[(b*CC+c)*2+1].
// ---------------------------------------------------------------------------
__device__ __forceinline__ void mid_body(const float* __restrict__ w_guide,
                                         int b, int r, int lane) {
    const float4* __restrict__ row =
        reinterpret_cast<const float4*>(w_guide + (size_t)r * CC);
    const float4* __restrict__ pp =
        reinterpret_cast<const float4*>(g_part + (size_t)b * CC * 2);

    float acc = 0.0f;
#pragma unroll
    for (int j = 0; j < 4; ++j) {
        float4 w  = row[lane + 32 * j];
        float4 a0 = pp[2 * (lane + 32 * j)];       // sums for channels 4k..4k+1
        float4 a1 = pp[2 * (lane + 32 * j) + 1];   // sums for channels 4k+2..4k+3
        acc = fmaf(w.x, a0.x + a0.y, acc);
        acc = fmaf(w.y, a0.z + a0.w, acc);
        acc = fmaf(w.z, a1.x + a1.y, acc);
        acc = fmaf(w.w, a1.z + a1.w, acc);
    }
#pragma unroll
    for (int o = 16; o > 0; o >>= 1)
        acc += __shfl_xor_sync(0xffffffffu, acc, o);
    if (lane == 0) {
        float v = acc * (1.0f / (float)HW);
        g_y1[b * RR + r] = fminf(fmaxf(v, 0.0f), 6.0f);
    }
}

// ---------------------------------------------------------------------------
// Unified phase kernel. CTA ranges (by blockIdx.x):
//   [0, nAdd)          : add  half-planes of batch addB  (nAdd = 1024 or 0)
//   [nAdd, nAdd+nMid)  : mid  batch midB (16 CTAs x 8 warps, or 0)
//   [nAdd+nMid, ...)   : red  half-planes of batch redB  (1024 or 0)
// All dependencies cross launch boundaries — no sync instructions.
// ---------------------------------------------------------------------------
__global__ __launch_bounds__(256) void phase_kernel(
    const float* __restrict__ x, float* __restrict__ out,
    const float* __restrict__ w_guide,
    const float* __restrict__ w_fuse,
    const float* __restrict__ bn_gamma, const float* __restrict__ bn_beta,
    const float* __restrict__ bn_mean,  const float* __restrict__ bn_var,
    int addB, int midB, int redB, int nAdd, int nMid) {
    const int bid = blockIdx.x;
    const int tid = threadIdx.x;

    if (bid < nAdd) {
        half_add(x, out, w_fuse, bn_gamma, bn_beta, bn_mean, bn_var,
                 addB, bid >> 1, bid & 1, tid);
    } else if (bid < nAdd + nMid) {
        const int r = (bid - nAdd) * 8 + (tid >> 5);
        mid_body(w_guide, midB, r, tid & 31);
    } else {
        const int rid = bid - nAdd - nMid;
        half_reduce(x, redB * CC + (rid >> 1), rid & 1, tid);
    }
}

extern "C" void kernel_launch(void* const* d_in, const int* in_sizes, int n_in,
                              void* d_out, int out_size) {
    const float* x        = (const float*)d_in[0];
    const float* w_guide  = (const float*)d_in[1];
    const float* w_fuse   = (const float*)d_in[2];
    const float* bn_gamma = (const float*)d_in[3];
    const float* bn_beta  = (const float*)d_in[4];
    const float* bn_mean  = (const float*)d_in[5];
    const float* bn_var   = (const float*)d_in[6];
    float* out = (float*)d_out;

    const int NMID = RR / 8;   // 16 CTAs, 8 warps each

    // Depth-2 pipeline: launch p does add(p-2) + mid(p-1) + red(p).
    for (int p = 0; p <= BB + 1; ++p) {
        const int addB = p - 2;
        const int midB = p - 1;
        const int redB = p;
        const int nAdd = (addB >= 0 && addB < BB) ? 2 * CC : 0;
        const int nMid = (midB >= 0 && midB < BB) ? NMID : 0;
        const int nRed = (redB < BB) ? 2 * CC : 0;
        phase_kernel<<<nAdd + nMid + nRed, 256>>>(
            x, out, w_guide, w_fuse, bn_gamma, bn_beta, bn_mean, bn_var,
            addB, midB, redB, nAdd, nMid);
    }
}